// round 2
// baseline (speedup 1.0000x reference)
#include <cuda_runtime.h>
#include <cstdint>
#include <cstddef>

#define NN 100000
#define EE 1600000
#define IN_CH 41
#define ED 8
#define HH 64
#define LL 3
#define GG 256
#define ATOM 21
#define EPSN 1e-5f
#define PAD 68  // padded row stride (floats) in shared

// ---------------- scratch (device globals; no allocation) ------------------
static __device__ float4 g_hbuf[(size_t)NN * HH / 4];
static __device__ float4 g_h2buf[(size_t)NN * HH / 4];
static __device__ float4 g_aggrbuf[(size_t)NN * HH / 4];

// ---------------- packed f32x2 helpers --------------------------------------
__device__ __forceinline__ unsigned long long pack2(float lo, float hi) {
    unsigned long long r;
    asm("mov.b64 %0, {%1,%2};" : "=l"(r) : "f"(lo), "f"(hi));
    return r;
}
__device__ __forceinline__ void unpack2(unsigned long long v, float& lo, float& hi) {
    asm("mov.b64 {%0,%1}, %2;" : "=f"(lo), "=f"(hi) : "l"(v));
}
__device__ __forceinline__ void ffma2(unsigned long long& d, unsigned long long a,
                                      unsigned long long b) {
    asm("fma.rn.f32x2 %0, %1, %2, %0;" : "+l"(d) : "l"(a), "l"(b));
}
// 16B shared load as two packed-f32x2 operands
__device__ __forceinline__ void lds_v2u64(unsigned long long& a, unsigned long long& b,
                                          const float* p) {
    unsigned int addr = (unsigned int)__cvta_generic_to_shared(p);
    asm("ld.shared.v2.u64 {%0,%1}, [%2];" : "=l"(a), "=l"(b) : "r"(addr));
}

__device__ __forceinline__ int lower_bound_dev(const int* __restrict__ arr, int n, int val) {
    int lo = 0, hi = n;
    while (lo < hi) {
        int mid = (lo + hi) >> 1;
        if (__ldg(&arr[mid]) < val) lo = mid + 1; else hi = mid;
    }
    return lo;
}

// 64x64 GEMM inner: 16 outputs per thread starting at fs, input row in shared.
__device__ __forceinline__ void gemm16(const float* __restrict__ sRow,
                                       const float* __restrict__ sW, int fs,
                                       unsigned long long acc[8]) {
    for (int k = 0; k < HH; k += 4) {
        float4 zv = *reinterpret_cast<const float4*>(&sRow[k]);
#pragma unroll
        for (int kk = 0; kk < 4; kk++) {
            float z = (&zv.x)[kk];
            unsigned long long z2 = pack2(z, z);
            const float* wr = &sW[(k + kk) * HH + fs];
            unsigned long long w0, w1, w2, w3, w4, w5, w6, w7;
            lds_v2u64(w0, w1, wr);
            lds_v2u64(w2, w3, wr + 4);
            lds_v2u64(w4, w5, wr + 8);
            lds_v2u64(w6, w7, wr + 12);
            ffma2(acc[0], z2, w0); ffma2(acc[1], z2, w1);
            ffma2(acc[2], z2, w2); ffma2(acc[3], z2, w3);
            ffma2(acc[4], z2, w4); ffma2(acc[5], z2, w5);
            ffma2(acc[6], z2, w6); ffma2(acc[7], z2, w7);
        }
    }
}

// ---------------- fused encoder: h = relu(relu(x@W1+b1)@W2+b2), dual branch -
__global__ void __launch_bounds__(256) k_encoder(
    const float* __restrict__ x,
    const float* __restrict__ lW1, const float* __restrict__ lb1,
    const float* __restrict__ lW2, const float* __restrict__ lb2,
    const float* __restrict__ pW1, const float* __restrict__ pb1,
    const float* __restrict__ pW2, const float* __restrict__ pb2,
    float* __restrict__ hout)
{
    __shared__ __align__(16) float sWl[HH * HH];
    __shared__ __align__(16) float sWp[HH * HH];
    __shared__ __align__(16) float sZ[64 * PAD];
    __shared__ __align__(16) float sBl[HH], sBp[HH];

    const int tid = threadIdx.x;
    const int n0 = blockIdx.x * 64;
    const int nl = tid >> 2;
    const int fs = (tid & 3) * 16;
    const int node = n0 + nl;
    const bool valid = node < NN;

    // phase 0: W1 (41x64) + b1 + stage x
    for (int i = tid; i < IN_CH * HH; i += 256) { sWl[i] = lW1[i]; sWp[i] = pW1[i]; }
    if (tid < HH) { sBl[tid] = lb1[tid]; sBp[tid] = pb1[tid]; }
    for (int c = tid; c < 64 * IN_CH; c += 256) {
        int n = c / IN_CH, k = c - n * IN_CH;
        sZ[n * PAD + k] = (n0 + n < NN) ? __ldg(&x[(size_t)(n0 + n) * IN_CH + k]) : 0.0f;
    }
    __syncthreads();

    // mask: residue part nonzero?
    const float* row = &sZ[nl * PAD];
    float s = 0.0f;
#pragma unroll
    for (int k = ATOM; k < IN_CH; k++) s += fabsf(row[k]);
    const bool prot = s > 1e-6f;
    const float* sW = prot ? sWp : sWl;
    const float* sB = prot ? sBp : sBl;

    // GEMM1 (K=41)
    unsigned long long acc[8];
#pragma unroll
    for (int j = 0; j < 8; j++) acc[j] = pack2(sB[fs + 2 * j], sB[fs + 2 * j + 1]);
    for (int k = 0; k < IN_CH; k++) {
        float z = row[k];
        unsigned long long z2 = pack2(z, z);
        const float* wr = &sW[k * HH + fs];
        unsigned long long w0, w1, w2, w3, w4, w5, w6, w7;
        lds_v2u64(w0, w1, wr);  lds_v2u64(w2, w3, wr + 4);
        lds_v2u64(w4, w5, wr + 8); lds_v2u64(w6, w7, wr + 12);
        ffma2(acc[0], z2, w0); ffma2(acc[1], z2, w1);
        ffma2(acc[2], z2, w2); ffma2(acc[3], z2, w3);
        ffma2(acc[4], z2, w4); ffma2(acc[5], z2, w5);
        ffma2(acc[6], z2, w6); ffma2(acc[7], z2, w7);
    }
    float tv[16];
#pragma unroll
    for (int j = 0; j < 8; j++) {
        float lo, hi; unpack2(acc[j], lo, hi);
        tv[2 * j] = fmaxf(lo, 0.f); tv[2 * j + 1] = fmaxf(hi, 0.f);
    }
    __syncthreads();

    // phase 1: t -> sZ, load W2
#pragma unroll
    for (int j = 0; j < 4; j++)
        *reinterpret_cast<float4*>(&sZ[nl * PAD + fs + 4 * j]) =
            make_float4(tv[4 * j], tv[4 * j + 1], tv[4 * j + 2], tv[4 * j + 3]);
    for (int i = tid; i < HH * HH / 4; i += 256) {
        ((float4*)sWl)[i] = ((const float4*)lW2)[i];
        ((float4*)sWp)[i] = ((const float4*)pW2)[i];
    }
    if (tid < HH) { sBl[tid] = lb2[tid]; sBp[tid] = pb2[tid]; }
    __syncthreads();

    const float* sW2 = prot ? sWp : sWl;
    const float* sB2 = prot ? sBp : sBl;
#pragma unroll
    for (int j = 0; j < 8; j++) acc[j] = pack2(sB2[fs + 2 * j], sB2[fs + 2 * j + 1]);
    gemm16(&sZ[nl * PAD], sW2, fs, acc);

    if (valid) {
        float4* op = reinterpret_cast<float4*>(hout + (size_t)node * HH + fs);
#pragma unroll
        for (int j = 0; j < 4; j++) {
            float lo0, hi0, lo1, hi1;
            unpack2(acc[2 * j], lo0, hi0);
            unpack2(acc[2 * j + 1], lo1, hi1);
            op[j] = make_float4(fmaxf(lo0, 0.f), fmaxf(hi0, 0.f),
                                fmaxf(lo1, 0.f), fmaxf(hi1, 0.f));
        }
    }
}

// ---------------- fused conv MLP: h2 = (relu((h+aggr)@W1+b1))@W2+b2 ---------
__global__ void __launch_bounds__(256) k_mlp(
    const float* __restrict__ hg, const float* __restrict__ ag,
    const float* __restrict__ W1, const float* __restrict__ b1,
    const float* __restrict__ W2, const float* __restrict__ b2,
    float* __restrict__ h2)
{
    __shared__ __align__(16) float sW[HH * HH];
    __shared__ __align__(16) float sZ[64 * PAD];
    __shared__ __align__(16) float sB[HH];

    const int tid = threadIdx.x;
    const int n0 = blockIdx.x * 64;
    const int nl = tid >> 2;
    const int fs = (tid & 3) * 16;
    const int node = n0 + nl;
    const bool valid = node < NN;

    for (int i = tid; i < HH * HH / 4; i += 256)
        ((float4*)sW)[i] = ((const float4*)W1)[i];
    if (tid < HH) sB[tid] = b1[tid];
    for (int c = tid; c < 64 * 16; c += 256) {
        int n = c >> 4, q = c & 15;
        float4 v = make_float4(0.f, 0.f, 0.f, 0.f);
        if (n0 + n < NN) {
            float4 a = __ldg(((const float4*)hg) + (size_t)(n0 + n) * 16 + q);
            float4 b = __ldg(((const float4*)ag) + (size_t)(n0 + n) * 16 + q);
            v = make_float4(a.x + b.x, a.y + b.y, a.z + b.z, a.w + b.w);
        }
        *reinterpret_cast<float4*>(&sZ[n * PAD + q * 4]) = v;
    }
    __syncthreads();

    unsigned long long acc[8];
#pragma unroll
    for (int j = 0; j < 8; j++) acc[j] = pack2(sB[fs + 2 * j], sB[fs + 2 * j + 1]);
    gemm16(&sZ[nl * PAD], sW, fs, acc);

    float tv[16];
#pragma unroll
    for (int j = 0; j < 8; j++) {
        float lo, hi; unpack2(acc[j], lo, hi);
        tv[2 * j] = fmaxf(lo, 0.f); tv[2 * j + 1] = fmaxf(hi, 0.f);
    }
    __syncthreads();  // all reads of sZ/sW done

    // t -> sZ (in place), W2 -> sW
#pragma unroll
    for (int j = 0; j < 4; j++)
        *reinterpret_cast<float4*>(&sZ[nl * PAD + fs + 4 * j]) =
            make_float4(tv[4 * j], tv[4 * j + 1], tv[4 * j + 2], tv[4 * j + 3]);
    for (int i = tid; i < HH * HH / 4; i += 256)
        ((float4*)sW)[i] = ((const float4*)W2)[i];
    if (tid < HH) sB[tid] = b2[tid];
    __syncthreads();

#pragma unroll
    for (int j = 0; j < 8; j++) acc[j] = pack2(sB[fs + 2 * j], sB[fs + 2 * j + 1]);
    gemm16(&sZ[nl * PAD], sW, fs, acc);

    if (valid) {
        float4* op = reinterpret_cast<float4*>(h2 + (size_t)node * HH + fs);
#pragma unroll
        for (int j = 0; j < 4; j++) {
            float lo0, hi0, lo1, hi1;
            unpack2(acc[2 * j], lo0, hi0);
            unpack2(acc[2 * j + 1], lo1, hi1);
            op[j] = make_float4(lo0, hi0, lo1, hi1);
        }
    }
}

// ---------------- edge kernel (persistent): aggr[dst] += relu(h[src]+ea@We+be)
__global__ void __launch_bounds__(256) k_edge(
    const float* __restrict__ h,
    const int* __restrict__ src, const int* __restrict__ dst,
    const float* __restrict__ ea,
    const float* __restrict__ We, const float* __restrict__ be,
    float* __restrict__ aggr)
{
    __shared__ __align__(16) float sW[ED * HH];
    __shared__ __align__(16) float sB[HH];
    for (int i = threadIdx.x; i < ED * HH; i += 256) sW[i] = We[i];
    if (threadIdx.x < HH) sB[threadIdx.x] = be[threadIdx.x];
    __syncthreads();

    const int le = threadIdx.x >> 4;
    const int lf = (threadIdx.x & 15) * 4;
    const float4 bias = *reinterpret_cast<const float4*>(&sB[lf]);
    const int stride = gridDim.x * 16;

    for (int e = blockIdx.x * 16 + le; e < EE; e += stride) {
        int s = __ldg(&src[e]);
        int d = __ldg(&dst[e]);
        const float4* eap = reinterpret_cast<const float4*>(ea + (size_t)e * ED);
        float4 a0 = __ldg(&eap[0]);
        float4 a1 = __ldg(&eap[1]);
        float4 hv = __ldg(reinterpret_cast<const float4*>(h + (size_t)s * HH + lf));
        float4 acc = bias;
#pragma unroll
        for (int k = 0; k < 4; k++) {
            float a = (&a0.x)[k];
            float4 wv = *reinterpret_cast<const float4*>(&sW[k * HH + lf]);
            acc.x = fmaf(a, wv.x, acc.x); acc.y = fmaf(a, wv.y, acc.y);
            acc.z = fmaf(a, wv.z, acc.z); acc.w = fmaf(a, wv.w, acc.w);
        }
#pragma unroll
        for (int k = 0; k < 4; k++) {
            float a = (&a1.x)[k];
            float4 wv = *reinterpret_cast<const float4*>(&sW[(k + 4) * HH + lf]);
            acc.x = fmaf(a, wv.x, acc.x); acc.y = fmaf(a, wv.y, acc.y);
            acc.z = fmaf(a, wv.z, acc.z); acc.w = fmaf(a, wv.w, acc.w);
        }
        float m0 = fmaxf(hv.x + acc.x, 0.f);
        float m1 = fmaxf(hv.y + acc.y, 0.f);
        float m2 = fmaxf(hv.z + acc.z, 0.f);
        float m3 = fmaxf(hv.w + acc.w, 0.f);
        float* p = aggr + (size_t)d * HH + lf;
        asm volatile("red.global.add.v4.f32 [%0], {%1,%2,%3,%4};"
                     :: "l"(p), "f"(m0), "f"(m1), "f"(m2), "f"(m3) : "memory");
    }
}

// ---------------- fused GraphNorm (stats + apply + relu), block per graph ---
__global__ void __launch_bounds__(256) k_norm(
    const float* __restrict__ h2, const int* __restrict__ batch,
    const float* __restrict__ w, const float* __restrict__ b,
    const float* __restrict__ alpha,
    float* __restrict__ hout)
{
    const int g = blockIdx.x;
    const int tid = threadIdx.x;
    __shared__ int sRange[2];
    if (tid < 2) sRange[tid] = lower_bound_dev(batch, NN, g + tid);
    __syncthreads();
    const int start = sRange[0], end = sRange[1];

    const int f = tid & 63;
    const int slot = tid >> 6;  // 0..3
    float s = 0.f, q = 0.f;
    for (int i = start + slot; i < end; i += 4) {
        float v = __ldg(&h2[(size_t)i * HH + f]);
        s += v;
        q = fmaf(v, v, q);
    }
    __shared__ float ss[256], sq[256];
    __shared__ float c1[HH], c2[HH];
    ss[tid] = s; sq[tid] = q;
    __syncthreads();
    if (tid < HH) {
        float S = ss[tid] + ss[tid + 64] + ss[tid + 128] + ss[tid + 192];
        float Q = sq[tid] + sq[tid + 64] + sq[tid + 128] + sq[tid + 192];
        float cnt = fmaxf((float)(end - start), 1.0f);
        float m = S / cnt;
        float m2 = Q / cnt;
        float a = __ldg(&alpha[tid]);
        float var = m2 - m * m * a * (2.0f - a);   // var of (h - a*m)
        float rstd = rsqrtf(var + EPSN);
        float wf = __ldg(&w[tid]);
        c1[tid] = wf * rstd;
        c2[tid] = __ldg(&b[tid]) - wf * rstd * a * m;
    }
    __syncthreads();
    const float c1f = c1[f], c2f = c2[f];
    for (int i = start + slot; i < end; i += 4)
        hout[(size_t)i * HH + f] = fmaxf(fmaf(c1f, __ldg(&h2[(size_t)i * HH + f]), c2f), 0.f);
}

// ---------------- pool + readout: block per graph ---------------------------
__global__ void __launch_bounds__(128) k_readout(
    const float* __restrict__ h, const int* __restrict__ batch,
    const float* __restrict__ W1, const float* __restrict__ b1,
    const float* __restrict__ W2, const float* __restrict__ b2,
    float* __restrict__ out)
{
    const int g = blockIdx.x;
    const int tid = threadIdx.x;
    __shared__ int sRange[2];
    if (tid < 2) sRange[tid] = lower_bound_dev(batch, NN, g + tid);
    __syncthreads();
    const int start = sRange[0], end = sRange[1];

    const int f = tid & 63;
    const int slot = tid >> 6;
    float s = 0.f;
    for (int i = start + slot; i < end; i += 2)
        s += __ldg(&h[(size_t)i * HH + f]);

    __shared__ float sp[128];
    __shared__ float pool[HH];
    __shared__ float tvs[HH];
    sp[tid] = s;
    __syncthreads();
    if (tid < HH) pool[tid] = sp[tid] + sp[tid + 64];
    __syncthreads();
    if (tid < HH) {
        float acc = __ldg(&b1[tid]);
#pragma unroll
        for (int k = 0; k < HH; k++)
            acc = fmaf(pool[k], __ldg(&W1[k * HH + tid]), acc);
        tvs[tid] = fmaxf(acc, 0.f) * __ldg(&W2[tid]);
    }
    __syncthreads();
    if (tid == 0) {
        float r = __ldg(b2);
#pragma unroll
        for (int k = 0; k < HH; k++) r += tvs[k];
        out[g] = r;
    }
}

// ---------------- launch ----------------------------------------------------
extern "C" void kernel_launch(void* const* d_in, const int* in_sizes, int n_in,
                              void* d_out, int out_size)
{
    const float* x       = (const float*)d_in[0];
    const int*   ei      = (const int*)d_in[1];
    const float* ea      = (const float*)d_in[2];
    const int*   batch   = (const int*)d_in[3];
    const float* lig_W1  = (const float*)d_in[4];
    const float* lig_b1  = (const float*)d_in[5];
    const float* lig_W2  = (const float*)d_in[6];
    const float* lig_b2  = (const float*)d_in[7];
    const float* prot_W1 = (const float*)d_in[8];
    const float* prot_b1 = (const float*)d_in[9];
    const float* prot_W2 = (const float*)d_in[10];
    const float* prot_b2 = (const float*)d_in[11];
    const float* conv_We = (const float*)d_in[12];
    const float* conv_be = (const float*)d_in[13];
    const float* conv_W1 = (const float*)d_in[14];
    const float* conv_b1 = (const float*)d_in[15];
    const float* conv_W2 = (const float*)d_in[16];
    const float* conv_b2 = (const float*)d_in[17];
    const float* norm_w  = (const float*)d_in[18];
    const float* norm_b  = (const float*)d_in[19];
    const float* norm_a  = (const float*)d_in[20];
    const float* out_W1  = (const float*)d_in[21];
    const float* out_b1  = (const float*)d_in[22];
    const float* out_W2  = (const float*)d_in[23];
    const float* out_b2  = (const float*)d_in[24];
    float* out = (float*)d_out;

    const int* src = ei;
    const int* dst = ei + EE;

    void *ph, *ph2, *pag;
    cudaGetSymbolAddress(&ph,  g_hbuf);
    cudaGetSymbolAddress(&ph2, g_h2buf);
    cudaGetSymbolAddress(&pag, g_aggrbuf);
    float* h    = (float*)ph;
    float* h2   = (float*)ph2;
    float* aggr = (float*)pag;

    const int mlpBlocks = (NN + 63) / 64;   // 1563
    const int edgeBlocks = 148 * 8;         // persistent-ish single wave

    k_encoder<<<mlpBlocks, 256>>>(x, lig_W1, lig_b1, lig_W2, lig_b2,
                                  prot_W1, prot_b1, prot_W2, prot_b2, h);

    for (int l = 0; l < LL; l++) {
        cudaMemsetAsync(aggr, 0, (size_t)NN * HH * sizeof(float));
        k_edge<<<edgeBlocks, 256>>>(h, src, dst, ea,
                                    conv_We + l * ED * HH, conv_be + l * HH, aggr);
        k_mlp<<<mlpBlocks, 256>>>(h, aggr, conv_W1 + l * HH * HH, conv_b1 + l * HH,
                                  conv_W2 + l * HH * HH, conv_b2 + l * HH, h2);
        k_norm<<<GG, 256>>>(h2, batch, norm_w + l * HH, norm_b + l * HH,
                            norm_a + l * HH, h);
    }

    k_readout<<<GG, 128>>>(h, batch, out_W1, out_b1, out_W2, out_b2, out);
}

// round 3
// speedup vs baseline: 1.4916x; 1.4916x over previous
#include <cuda_runtime.h>
#include <cstdint>
#include <cstddef>

#define NN 100000
#define EE 1600000
#define IN_CH 41
#define ED 8
#define HH 64
#define LL 3
#define GG 256
#define ATOM 21
#define EPSN 1e-5f
#define PADT 65  // odd stride -> conflict-free scalar LDS per-row

// ---------------- scratch (device globals; no allocation) ------------------
static __device__ float4 g_hbuf[(size_t)NN * HH / 4];
static __device__ float4 g_h2buf[(size_t)NN * HH / 4];
static __device__ float4 g_aggrbuf[(size_t)NN * HH / 4];
static __device__ float  g_SQ[2 * GG * HH];      // [S | Q]
static __device__ float  g_coef[2 * GG * HH];    // [c1 | c2]
static __device__ float  g_cnt[GG];

// ---------------- packed f32x2 helpers --------------------------------------
__device__ __forceinline__ unsigned long long pack2(float lo, float hi) {
    unsigned long long r;
    asm("mov.b64 %0, {%1,%2};" : "=l"(r) : "f"(lo), "f"(hi));
    return r;
}
__device__ __forceinline__ void unpack2(unsigned long long v, float& lo, float& hi) {
    asm("mov.b64 {%0,%1}, %2;" : "=f"(lo), "=f"(hi) : "l"(v));
}
__device__ __forceinline__ void ffma2(unsigned long long& d, unsigned long long a,
                                      unsigned long long b) {
    asm("fma.rn.f32x2 %0, %1, %2, %0;" : "+l"(d) : "l"(a), "l"(b));
}
__device__ __forceinline__ void lds_v2u64(unsigned long long& a, unsigned long long& b,
                                          const float* p) {
    unsigned int addr = (unsigned int)__cvta_generic_to_shared(p);
    asm("ld.shared.v2.u64 {%0,%1}, [%2];" : "=l"(a), "=l"(b) : "r"(addr));
}

__device__ __forceinline__ int lower_bound_dev(const int* __restrict__ arr, int n, int val) {
    int lo = 0, hi = n;
    while (lo < hi) {
        int mid = (lo + hi) >> 1;
        if (__ldg(&arr[mid]) < val) lo = mid + 1; else hi = mid;
    }
    return lo;
}

// one k-step: acc[0..31] += z2 * W[k][0..63] (broadcast shared reads)
__device__ __forceinline__ void kstep(const float* __restrict__ wr,
                                      unsigned long long z2,
                                      unsigned long long* __restrict__ acc) {
#pragma unroll
    for (int j = 0; j < 16; j++) {
        unsigned long long w0, w1;
        lds_v2u64(w0, w1, wr + j * 4);
        ffma2(acc[2 * j], z2, w0);
        ffma2(acc[2 * j + 1], z2, w1);
    }
}

// ================= fused conv MLP: h2 = (relu((h+aggr)@W1+b1))@W2+b2 ========
// 128 threads = 128 nodes per block. Broadcast W from shared; t in private
// shared row (stride 65, conflict-free); z prefetched from global in float4s.
__global__ void __launch_bounds__(128) k_mlp(
    const float* __restrict__ hg, const float* __restrict__ ag,
    const float* __restrict__ W1, const float* __restrict__ b1,
    const float* __restrict__ W2, const float* __restrict__ b2,
    float* __restrict__ h2out)
{
    extern __shared__ float smem[];
    float* sW1 = smem;                  // 4096
    float* sW2 = smem + 4096;           // 4096
    float* sT  = smem + 8192;           // 128*65 = 8320
    float* sB1 = smem + 16512;          // 64
    float* sB2 = smem + 16576;          // 64

    const int tid = threadIdx.x;
    const int node = blockIdx.x * 128 + tid;
    const int nload = node < NN ? node : NN - 1;
    const bool valid = node < NN;

    for (int i = tid; i < 1024; i += 128) {
        ((float4*)sW1)[i] = __ldg(((const float4*)W1) + i);
        ((float4*)sW2)[i] = __ldg(((const float4*)W2) + i);
    }
    if (tid < HH) { sB1[tid] = __ldg(&b1[tid]); sB2[tid] = __ldg(&b2[tid]); }
    __syncthreads();

    const float4* hp = ((const float4*)hg) + (size_t)nload * 16;
    const float4* ap = ((const float4*)ag) + (size_t)nload * 16;

    unsigned long long acc[32];
#pragma unroll
    for (int j = 0; j < 32; j++) acc[j] = pack2(sB1[2 * j], sB1[2 * j + 1]);

    // GEMM1 with prefetched z chunks
    float4 hv = __ldg(hp), av = __ldg(ap);
    for (int c = 0; c < 16; c++) {
        float4 hn, an;
        if (c < 15) { hn = __ldg(hp + c + 1); an = __ldg(ap + c + 1); }
        float z0 = hv.x + av.x, z1 = hv.y + av.y, z2c = hv.z + av.z, z3 = hv.w + av.w;
        const float* wr = sW1 + (c * 4) * HH;
        kstep(wr,          pack2(z0, z0), acc);
        kstep(wr + HH,     pack2(z1, z1), acc);
        kstep(wr + 2 * HH, pack2(z2c, z2c), acc);
        kstep(wr + 3 * HH, pack2(z3, z3), acc);
        hv = hn; av = an;
    }

    // relu -> private shared row
    float* trow = sT + tid * PADT;
#pragma unroll
    for (int j = 0; j < 32; j++) {
        float lo, hi; unpack2(acc[j], lo, hi);
        trow[2 * j] = fmaxf(lo, 0.f);
        trow[2 * j + 1] = fmaxf(hi, 0.f);
    }

    // GEMM2 (z scalar from own shared row; no sync needed)
#pragma unroll
    for (int j = 0; j < 32; j++) acc[j] = pack2(sB2[2 * j], sB2[2 * j + 1]);
    for (int k = 0; k < HH; k++) {
        float zv = trow[k];
        kstep(sW2 + k * HH, pack2(zv, zv), acc);
    }

    if (valid) {
        float4* op = (float4*)(h2out + (size_t)node * HH);
#pragma unroll
        for (int q = 0; q < 16; q++) {
            float a0, a1, a2, a3;
            unpack2(acc[2 * q], a0, a1);
            unpack2(acc[2 * q + 1], a2, a3);
            op[q] = make_float4(a0, a1, a2, a3);
        }
    }
}

// ================= fused encoder (dual branch) ===============================
__global__ void __launch_bounds__(128) k_encoder(
    const float* __restrict__ x,
    const float* __restrict__ lW1, const float* __restrict__ lb1,
    const float* __restrict__ lW2, const float* __restrict__ lb2,
    const float* __restrict__ pW1, const float* __restrict__ pb1,
    const float* __restrict__ pW2, const float* __restrict__ pb2,
    float* __restrict__ hout)
{
    extern __shared__ float smem[];
    float* sWl1 = smem;            // 2624
    float* sWp1 = smem + 2624;     // 2624
    float* sWl2 = smem + 5248;     // 4096
    float* sWp2 = smem + 9344;     // 4096
    float* sT   = smem + 13440;    // 8320
    float* sB   = smem + 21760;    // 256: lb1 pb1 lb2 pb2

    const int tid = threadIdx.x;
    const int n0 = blockIdx.x * 128;
    const int node = n0 + tid;
    const bool valid = node < NN;

    for (int i = tid; i < 656; i += 128) {
        ((float4*)sWl1)[i] = __ldg(((const float4*)lW1) + i);
        ((float4*)sWp1)[i] = __ldg(((const float4*)pW1) + i);
    }
    for (int i = tid; i < 1024; i += 128) {
        ((float4*)sWl2)[i] = __ldg(((const float4*)lW2) + i);
        ((float4*)sWp2)[i] = __ldg(((const float4*)pW2) + i);
    }
    if (tid < HH) {
        sB[tid] = __ldg(&lb1[tid]); sB[64 + tid] = __ldg(&pb1[tid]);
        sB[128 + tid] = __ldg(&lb2[tid]); sB[192 + tid] = __ldg(&pb2[tid]);
    }
    // stage x rows (stride PADT)
    for (int c = tid; c < 128 * IN_CH; c += 128) {
        int n = c / IN_CH, k = c - n * IN_CH;
        sT[n * PADT + k] = (n0 + n < NN) ? __ldg(&x[(size_t)(n0 + n) * IN_CH + k]) : 0.f;
    }
    __syncthreads();

    float* trow = sT + tid * PADT;
    float s = 0.f;
#pragma unroll
    for (int k = ATOM; k < IN_CH; k++) s += fabsf(trow[k]);
    const bool prot = s > 1e-6f;
    const float* sW1 = prot ? sWp1 : sWl1;
    const float* sW2 = prot ? sWp2 : sWl2;
    const float* b1 = prot ? (sB + 64) : sB;
    const float* b2 = prot ? (sB + 192) : (sB + 128);

    unsigned long long acc[32];
#pragma unroll
    for (int j = 0; j < 32; j++) acc[j] = pack2(b1[2 * j], b1[2 * j + 1]);
    for (int k = 0; k < IN_CH; k++) {
        float zv = trow[k];
        kstep(sW1 + k * HH, pack2(zv, zv), acc);
    }
    // relu -> own row (x fully consumed)
#pragma unroll
    for (int j = 0; j < 32; j++) {
        float lo, hi; unpack2(acc[j], lo, hi);
        trow[2 * j] = fmaxf(lo, 0.f);
        trow[2 * j + 1] = fmaxf(hi, 0.f);
    }
#pragma unroll
    for (int j = 0; j < 32; j++) acc[j] = pack2(b2[2 * j], b2[2 * j + 1]);
    for (int k = 0; k < HH; k++) {
        float zv = trow[k];
        kstep(sW2 + k * HH, pack2(zv, zv), acc);
    }
    if (valid) {
        float4* op = (float4*)(hout + (size_t)node * HH);
#pragma unroll
        for (int q = 0; q < 16; q++) {
            float a0, a1, a2, a3;
            unpack2(acc[2 * q], a0, a1);
            unpack2(acc[2 * q + 1], a2, a3);
            op[q] = make_float4(fmaxf(a0, 0.f), fmaxf(a1, 0.f),
                                fmaxf(a2, 0.f), fmaxf(a3, 0.f));
        }
    }
}

// ================= edge kernel (persistent) ==================================
__global__ void __launch_bounds__(256) k_edge(
    const float* __restrict__ h,
    const int* __restrict__ src, const int* __restrict__ dst,
    const float* __restrict__ ea,
    const float* __restrict__ We, const float* __restrict__ be,
    float* __restrict__ aggr)
{
    __shared__ __align__(16) float sW[ED * HH];
    __shared__ __align__(16) float sB[HH];
    for (int i = threadIdx.x; i < ED * HH; i += 256) sW[i] = We[i];
    if (threadIdx.x < HH) sB[threadIdx.x] = be[threadIdx.x];
    __syncthreads();

    const int le = threadIdx.x >> 4;
    const int lf = (threadIdx.x & 15) * 4;
    const float4 bias = *reinterpret_cast<const float4*>(&sB[lf]);
    const int stride = gridDim.x * 16;

    for (int e = blockIdx.x * 16 + le; e < EE; e += stride) {
        int s = __ldg(&src[e]);
        int d = __ldg(&dst[e]);
        const float4* eap = reinterpret_cast<const float4*>(ea + (size_t)e * ED);
        float4 a0 = __ldg(&eap[0]);
        float4 a1 = __ldg(&eap[1]);
        float4 hv = __ldg(reinterpret_cast<const float4*>(h + (size_t)s * HH + lf));
        float4 acc = bias;
#pragma unroll
        for (int k = 0; k < 4; k++) {
            float a = (&a0.x)[k];
            float4 wv = *reinterpret_cast<const float4*>(&sW[k * HH + lf]);
            acc.x = fmaf(a, wv.x, acc.x); acc.y = fmaf(a, wv.y, acc.y);
            acc.z = fmaf(a, wv.z, acc.z); acc.w = fmaf(a, wv.w, acc.w);
        }
#pragma unroll
        for (int k = 0; k < 4; k++) {
            float a = (&a1.x)[k];
            float4 wv = *reinterpret_cast<const float4*>(&sW[(k + 4) * HH + lf]);
            acc.x = fmaf(a, wv.x, acc.x); acc.y = fmaf(a, wv.y, acc.y);
            acc.z = fmaf(a, wv.z, acc.z); acc.w = fmaf(a, wv.w, acc.w);
        }
        float m0 = fmaxf(hv.x + acc.x, 0.f);
        float m1 = fmaxf(hv.y + acc.y, 0.f);
        float m2 = fmaxf(hv.z + acc.z, 0.f);
        float m3 = fmaxf(hv.w + acc.w, 0.f);
        float* p = aggr + (size_t)d * HH + lf;
        asm volatile("red.global.add.v4.f32 [%0], {%1,%2,%3,%4};"
                     :: "l"(p), "f"(m0), "f"(m1), "f"(m2), "f"(m3) : "memory");
    }
}

// ================= GraphNorm: chunked stats -> S,Q ==========================
__global__ void __launch_bounds__(256) k_stats(
    const float* __restrict__ h2, const int* __restrict__ batch,
    float* __restrict__ SQ)
{
    const int c0 = blockIdx.x * 256;
    const int cend = (c0 + 256 < NN) ? c0 + 256 : NN;
    const int tid = threadIdx.x;
    const int f = tid & 63;
    const int slot = tid >> 6;

    const int g0 = __ldg(&batch[c0]);
    const int g1 = __ldg(&batch[cend - 1]);
    const int span = g1 - g0 + 1;

    __shared__ float sS[8 * 64], sQ[8 * 64];
    if (span <= 8) {
        for (int i = tid; i < 512; i += 256) { sS[i] = 0.f; sQ[i] = 0.f; }
        __syncthreads();
        for (int i = c0 + slot; i < cend; i += 4) {
            float v = __ldg(&h2[(size_t)i * HH + f]);
            int gi = __ldg(&batch[i]) - g0;
            atomicAdd(&sS[gi * 64 + f], v);
            atomicAdd(&sQ[gi * 64 + f], v * v);
        }
        __syncthreads();
        for (int i2 = tid; i2 < span * 64; i2 += 256) {
            int gg = g0 + (i2 >> 6);
            atomicAdd(&SQ[gg * 64 + (i2 & 63)], sS[i2]);
            atomicAdd(&SQ[GG * HH + gg * 64 + (i2 & 63)], sQ[i2]);
        }
    } else {
        for (int i = c0 + slot; i < cend; i += 4) {
            float v = __ldg(&h2[(size_t)i * HH + f]);
            int gg = __ldg(&batch[i]);
            atomicAdd(&SQ[gg * 64 + f], v);
            atomicAdd(&SQ[GG * HH + gg * 64 + f], v * v);
        }
    }
}

// ================= per-graph counts (runs once) ==============================
__global__ void k_counts(const int* __restrict__ batch, float* __restrict__ cnt)
{
    int g = blockIdx.x * blockDim.x + threadIdx.x;
    if (g >= GG) return;
    int a = lower_bound_dev(batch, NN, g);
    int b = lower_bound_dev(batch, NN, g + 1);
    int c = b - a;
    cnt[g] = (float)(c > 0 ? c : 1);
}

// ================= GraphNorm: coefficient table ==============================
__global__ void __launch_bounds__(256) k_coef(
    const float* __restrict__ SQ, const float* __restrict__ cnt,
    const float* __restrict__ w, const float* __restrict__ b,
    const float* __restrict__ alpha, float* __restrict__ coef)
{
    int idx = blockIdx.x * 256 + threadIdx.x;  // GG*HH
    int g = idx >> 6, f = idx & 63;
    float c = __ldg(&cnt[g]);
    float S = __ldg(&SQ[idx]);
    float Q = __ldg(&SQ[GG * HH + idx]);
    float m = S / c;
    float m2 = Q / c;
    float a = __ldg(&alpha[f]);
    float var = m2 - m * m * a * (2.0f - a);
    float rstd = rsqrtf(var + EPSN);
    float wf = __ldg(&w[f]);
    coef[idx] = wf * rstd;
    coef[GG * HH + idx] = __ldg(&b[f]) - wf * rstd * a * m;
}

// ================= GraphNorm: elementwise apply + relu =======================
__global__ void __launch_bounds__(256) k_apply(
    const float* __restrict__ h2, const int* __restrict__ batch,
    const float* __restrict__ coef, float* __restrict__ hout)
{
    int idx = blockIdx.x * 256 + threadIdx.x;  // NN*16 float4s
    if (idx >= NN * 16) return;
    int node = idx >> 4, q = idx & 15;
    int g = __ldg(&batch[node]);
    float4 v = __ldg(((const float4*)h2) + idx);
    float4 c1 = __ldg(((const float4*)coef) + g * 16 + q);
    float4 c2 = __ldg(((const float4*)(coef + GG * HH)) + g * 16 + q);
    float4 o;
    o.x = fmaxf(fmaf(c1.x, v.x, c2.x), 0.f);
    o.y = fmaxf(fmaf(c1.y, v.y, c2.y), 0.f);
    o.z = fmaxf(fmaf(c1.z, v.z, c2.z), 0.f);
    o.w = fmaxf(fmaf(c1.w, v.w, c2.w), 0.f);
    ((float4*)hout)[idx] = o;
}

// ================= pool + readout ============================================
__global__ void __launch_bounds__(128) k_readout(
    const float* __restrict__ h, const int* __restrict__ batch,
    const float* __restrict__ W1, const float* __restrict__ b1,
    const float* __restrict__ W2, const float* __restrict__ b2,
    float* __restrict__ out)
{
    const int g = blockIdx.x;
    const int tid = threadIdx.x;
    __shared__ int sRange[2];
    if (tid < 2) sRange[tid] = lower_bound_dev(batch, NN, g + tid);
    __syncthreads();
    const int start = sRange[0], end = sRange[1];

    const int f = tid & 63;
    const int slot = tid >> 6;
    float s = 0.f;
    for (int i = start + slot; i < end; i += 2)
        s += __ldg(&h[(size_t)i * HH + f]);

    __shared__ float sp[128];
    __shared__ float pool[HH];
    __shared__ float tvs[HH];
    sp[tid] = s;
    __syncthreads();
    if (tid < HH) pool[tid] = sp[tid] + sp[tid + 64];
    __syncthreads();
    if (tid < HH) {
        float acc = __ldg(&b1[tid]);
#pragma unroll
        for (int k = 0; k < HH; k++)
            acc = fmaf(pool[k], __ldg(&W1[k * HH + tid]), acc);
        tvs[tid] = fmaxf(acc, 0.f) * __ldg(&W2[tid]);
    }
    __syncthreads();
    if (tid == 0) {
        float r = __ldg(b2);
#pragma unroll
        for (int k = 0; k < HH; k++) r += tvs[k];
        out[g] = r;
    }
}

// ================= launch ====================================================
extern "C" void kernel_launch(void* const* d_in, const int* in_sizes, int n_in,
                              void* d_out, int out_size)
{
    const float* x       = (const float*)d_in[0];
    const int*   ei      = (const int*)d_in[1];
    const float* ea      = (const float*)d_in[2];
    const int*   batch   = (const int*)d_in[3];
    const float* lig_W1  = (const float*)d_in[4];
    const float* lig_b1  = (const float*)d_in[5];
    const float* lig_W2  = (const float*)d_in[6];
    const float* lig_b2  = (const float*)d_in[7];
    const float* prot_W1 = (const float*)d_in[8];
    const float* prot_b1 = (const float*)d_in[9];
    const float* prot_W2 = (const float*)d_in[10];
    const float* prot_b2 = (const float*)d_in[11];
    const float* conv_We = (const float*)d_in[12];
    const float* conv_be = (const float*)d_in[13];
    const float* conv_W1 = (const float*)d_in[14];
    const float* conv_b1 = (const float*)d_in[15];
    const float* conv_W2 = (const float*)d_in[16];
    const float* conv_b2 = (const float*)d_in[17];
    const float* norm_w  = (const float*)d_in[18];
    const float* norm_b  = (const float*)d_in[19];
    const float* norm_a  = (const float*)d_in[20];
    const float* out_W1  = (const float*)d_in[21];
    const float* out_b1  = (const float*)d_in[22];
    const float* out_W2  = (const float*)d_in[23];
    const float* out_b2  = (const float*)d_in[24];
    float* out = (float*)d_out;

    const int* src = ei;
    const int* dst = ei + EE;

    void *ph, *ph2, *pag, *psq, *pcoef, *pcnt;
    cudaGetSymbolAddress(&ph,   g_hbuf);
    cudaGetSymbolAddress(&ph2,  g_h2buf);
    cudaGetSymbolAddress(&pag,  g_aggrbuf);
    cudaGetSymbolAddress(&psq,  g_SQ);
    cudaGetSymbolAddress(&pcoef, g_coef);
    cudaGetSymbolAddress(&pcnt, g_cnt);
    float* h    = (float*)ph;
    float* h2   = (float*)ph2;
    float* aggr = (float*)pag;
    float* SQ   = (float*)psq;
    float* coef = (float*)pcoef;
    float* cnt  = (float*)pcnt;

    static bool attr_done = false;
    if (!attr_done) {
        cudaFuncSetAttribute(k_mlp, cudaFuncAttributeMaxDynamicSharedMemorySize, 16640 * 4);
        cudaFuncSetAttribute(k_encoder, cudaFuncAttributeMaxDynamicSharedMemorySize, 22016 * 4);
        attr_done = true;
    }

    const int nodeBlocks = (NN + 127) / 128;     // 782
    const int edgeBlocks = 148 * 8;
    const int applyBlocks = (NN * 16 + 255) / 256;

    k_counts<<<1, 256>>>(batch, cnt);
    k_encoder<<<nodeBlocks, 128, 22016 * 4>>>(x, lig_W1, lig_b1, lig_W2, lig_b2,
                                              prot_W1, prot_b1, prot_W2, prot_b2, h);

    for (int l = 0; l < LL; l++) {
        cudaMemsetAsync(aggr, 0, (size_t)NN * HH * sizeof(float));
        k_edge<<<edgeBlocks, 256>>>(h, src, dst, ea,
                                    conv_We + l * ED * HH, conv_be + l * HH, aggr);
        k_mlp<<<nodeBlocks, 128, 16640 * 4>>>(h, aggr, conv_W1 + l * HH * HH,
                                              conv_b1 + l * HH,
                                              conv_W2 + l * HH * HH,
                                              conv_b2 + l * HH, h2);
        cudaMemsetAsync(SQ, 0, 2 * GG * HH * sizeof(float));
        k_stats<<<(NN + 255) / 256, 256>>>(h2, batch, SQ);
        k_coef<<<GG * HH / 256, 256>>>(SQ, cnt, norm_w + l * HH, norm_b + l * HH,
                                       norm_a + l * HH, coef);
        k_apply<<<applyBlocks, 256>>>(h2, batch, coef, h);
    }

    k_readout<<<GG, 128>>>(h, batch, out_W1, out_b1, out_W2, out_b2, out);
}

// round 5
// speedup vs baseline: 1.6578x; 1.1115x over previous
#include <cuda_runtime.h>
#include <cstdint>
#include <cstddef>

#define NN 100000
#define EE 1600000
#define IN_CH 41
#define ED 8
#define HH 64
#define LL 3
#define GG 256
#define ATOM 21
#define EPSN 1e-5f
#define PADT 65

// ---------------- scratch (device globals; no allocation) ------------------
static __device__ float4 g_hbuf[(size_t)NN * HH / 4];
static __device__ float4 g_h2buf[(size_t)NN * HH / 4];
static __device__ float4 g_aggrbuf[(size_t)NN * HH / 4];
static __device__ float  g_SQ[2 * GG * HH];
static __device__ float  g_coef[2 * GG * HH];
static __device__ float  g_cnt[GG];

// ---------------- packed f32x2 helpers --------------------------------------
__device__ __forceinline__ unsigned long long pack2(float lo, float hi) {
    unsigned long long r;
    asm("mov.b64 %0, {%1,%2};" : "=l"(r) : "f"(lo), "f"(hi));
    return r;
}
__device__ __forceinline__ void unpack2(unsigned long long v, float& lo, float& hi) {
    asm("mov.b64 {%0,%1}, %2;" : "=f"(lo), "=f"(hi) : "l"(v));
}
__device__ __forceinline__ void ffma2(unsigned long long& d, unsigned long long a,
                                      unsigned long long b) {
    asm("fma.rn.f32x2 %0, %1, %2, %0;" : "+l"(d) : "l"(a), "l"(b));
}
__device__ __forceinline__ void lds_2u64(unsigned long long& a, unsigned long long& b,
                                         const void* p) {
    unsigned int addr = (unsigned int)__cvta_generic_to_shared(p);
    asm("ld.shared.v2.u64 {%0,%1}, [%2];" : "=l"(a), "=l"(b) : "r"(addr));
}
__device__ __forceinline__ void sts_2u64(void* p, unsigned long long a,
                                         unsigned long long b) {
    unsigned int addr = (unsigned int)__cvta_generic_to_shared(p);
    asm volatile("st.shared.v2.u64 [%0], {%1,%2};" :: "r"(addr), "l"(a), "l"(b));
}

__device__ __forceinline__ int lower_bound_dev(const int* __restrict__ arr, int n, int val) {
    int lo = 0, hi = n;
    while (lo < hi) {
        int mid = (lo + hi) >> 1;
        if (__ldg(&arr[mid]) < val) lo = mid + 1; else hi = mid;
    }
    return lo;
}

// broadcast kstep (encoder): acc[0..31] += z2 * W[k][0..63]
__device__ __forceinline__ void kstep(const float* __restrict__ wr,
                                      unsigned long long z2,
                                      unsigned long long* __restrict__ acc) {
#pragma unroll
    for (int j = 0; j < 16; j++) {
        unsigned long long w0, w1;
        lds_2u64(w0, w1, wr + j * 4);
        ffma2(acc[2 * j], z2, w0);
        ffma2(acc[2 * j + 1], z2, w1);
    }
}

// ================= fused conv MLP (retiled) =================================
// zp[k][pair] layout: u64 = (z[2p][k], z[2p+1][k]); stride 66 u64 per k-row.
// thread: og = tid&15 (4 outs), pg = tid>>4 (8 node-pairs). acc = 4x8 u64.
#define ZP_STRIDE 66
#define MLP_SMEM (64 * ZP_STRIDE * 8 + 4096 * 4 + 128 * 4)  // 50688 B

__global__ void __launch_bounds__(128, 4) k_mlp(
    const float* __restrict__ hg, const float* __restrict__ ag,
    const float* __restrict__ W1, const float* __restrict__ b1,
    const float* __restrict__ W2, const float* __restrict__ b2,
    float* __restrict__ h2out)
{
    extern __shared__ char smemraw[];
    unsigned long long* zp = (unsigned long long*)smemraw;         // [64][66]
    float* sW = (float*)(smemraw + 64 * ZP_STRIDE * 8);            // 4096 f
    float* sB = (float*)(smemraw + 64 * ZP_STRIDE * 8 + 16384);    // 128 f

    const int tid = threadIdx.x;
    const int og = tid & 15;
    const int pg = tid >> 4;
    const int n0 = blockIdx.x * 128;

    // load W1, biases
    for (int i = tid; i < 1024; i += 128)
        ((float4*)sW)[i] = __ldg(((const float4*)W1) + i);
    if (tid < HH) { sB[tid] = __ldg(&b1[tid]); sB[64 + tid] = __ldg(&b2[tid]); }

    // stage z = h + aggr as packed pairs (q-fast: coalesced global reads)
    for (int task = tid; task < 1024; task += 128) {
        int p = task >> 4, q = task & 15;
        int na = n0 + 2 * p;
        int naL = na < NN ? na : NN - 1;
        int nbL = na + 1 < NN ? na + 1 : NN - 1;
        float4 va = __ldg(((const float4*)hg) + (size_t)naL * 16 + q);
        float4 sa = __ldg(((const float4*)ag) + (size_t)naL * 16 + q);
        float4 vb = __ldg(((const float4*)hg) + (size_t)nbL * 16 + q);
        float4 sb = __ldg(((const float4*)ag) + (size_t)nbL * 16 + q);
        va.x += sa.x; va.y += sa.y; va.z += sa.z; va.w += sa.w;
        vb.x += sb.x; vb.y += sb.y; vb.z += sb.z; vb.w += sb.w;
        int k4 = q * 4;
        zp[(k4 + 0) * ZP_STRIDE + p] = pack2(va.x, vb.x);
        zp[(k4 + 1) * ZP_STRIDE + p] = pack2(va.y, vb.y);
        zp[(k4 + 2) * ZP_STRIDE + p] = pack2(va.z, vb.z);
        zp[(k4 + 3) * ZP_STRIDE + p] = pack2(va.w, vb.w);
    }
    __syncthreads();

    unsigned long long acc[32];  // acc[o*8+j]
#pragma unroll
    for (int o = 0; o < 4; o++) {
        float bv = sB[og * 4 + o];
        unsigned long long bb = pack2(bv, bv);
#pragma unroll
        for (int j = 0; j < 8; j++) acc[o * 8 + j] = bb;
    }

    // GEMM1
#pragma unroll 4
    for (int k = 0; k < HH; k++) {
        const unsigned long long* zr = zp + k * ZP_STRIDE + pg * 8;
        unsigned long long z0, z1, z2, z3, z4, z5, z6, z7;
        lds_2u64(z0, z1, zr);     lds_2u64(z2, z3, zr + 2);
        lds_2u64(z4, z5, zr + 4); lds_2u64(z6, z7, zr + 6);
        float4 wv = *(const float4*)(sW + k * HH + og * 4);
#pragma unroll
        for (int o = 0; o < 4; o++) {
            unsigned long long ww = pack2((&wv.x)[o], (&wv.x)[o]);
            ffma2(acc[o * 8 + 0], z0, ww); ffma2(acc[o * 8 + 1], z1, ww);
            ffma2(acc[o * 8 + 2], z2, ww); ffma2(acc[o * 8 + 3], z3, ww);
            ffma2(acc[o * 8 + 4], z4, ww); ffma2(acc[o * 8 + 5], z5, ww);
            ffma2(acc[o * 8 + 6], z6, ww); ffma2(acc[o * 8 + 7], z7, ww);
        }
    }
    __syncthreads();  // all zp reads done

    // relu(t) -> zp (thread owns rows og*4..og*4+3, cols pg*8..pg*8+7)
#pragma unroll
    for (int o = 0; o < 4; o++) {
        unsigned long long* tr = zp + (og * 4 + o) * ZP_STRIDE + pg * 8;
#pragma unroll
        for (int j = 0; j < 8; j += 2) {
            float a0, a1, b0v, b1v;
            unpack2(acc[o * 8 + j], a0, a1);
            unpack2(acc[o * 8 + j + 1], b0v, b1v);
            sts_2u64(tr + j, pack2(fmaxf(a0, 0.f), fmaxf(a1, 0.f)),
                             pack2(fmaxf(b0v, 0.f), fmaxf(b1v, 0.f)));
        }
    }
    // load W2 over W1
    for (int i = tid; i < 1024; i += 128)
        ((float4*)sW)[i] = __ldg(((const float4*)W2) + i);
    __syncthreads();

#pragma unroll
    for (int o = 0; o < 4; o++) {
        float bv = sB[64 + og * 4 + o];
        unsigned long long bb = pack2(bv, bv);
#pragma unroll
        for (int j = 0; j < 8; j++) acc[o * 8 + j] = bb;
    }

    // GEMM2
#pragma unroll 4
    for (int k = 0; k < HH; k++) {
        const unsigned long long* zr = zp + k * ZP_STRIDE + pg * 8;
        unsigned long long z0, z1, z2, z3, z4, z5, z6, z7;
        lds_2u64(z0, z1, zr);     lds_2u64(z2, z3, zr + 2);
        lds_2u64(z4, z5, zr + 4); lds_2u64(z6, z7, zr + 6);
        float4 wv = *(const float4*)(sW + k * HH + og * 4);
#pragma unroll
        for (int o = 0; o < 4; o++) {
            unsigned long long ww = pack2((&wv.x)[o], (&wv.x)[o]);
            ffma2(acc[o * 8 + 0], z0, ww); ffma2(acc[o * 8 + 1], z1, ww);
            ffma2(acc[o * 8 + 2], z2, ww); ffma2(acc[o * 8 + 3], z3, ww);
            ffma2(acc[o * 8 + 4], z4, ww); ffma2(acc[o * 8 + 5], z5, ww);
            ffma2(acc[o * 8 + 6], z6, ww); ffma2(acc[o * 8 + 7], z7, ww);
        }
    }

    // store: per pair j, one float4 per node
#pragma unroll
    for (int j = 0; j < 8; j++) {
        int p = pg * 8 + j;
        int ne = n0 + 2 * p, no = ne + 1;
        float e0, d0, e1, d1, e2, d2, e3, d3;
        unpack2(acc[0 * 8 + j], e0, d0);
        unpack2(acc[1 * 8 + j], e1, d1);
        unpack2(acc[2 * 8 + j], e2, d2);
        unpack2(acc[3 * 8 + j], e3, d3);
        if (ne < NN)
            *(float4*)(h2out + (size_t)ne * HH + og * 4) = make_float4(e0, e1, e2, e3);
        if (no < NN)
            *(float4*)(h2out + (size_t)no * HH + og * 4) = make_float4(d0, d1, d2, d3);
    }
}

// ================= fused encoder (dual branch, two-phase W reuse) ===========
#define ENC_SMEM ((8192 + 128 * PADT + 256) * 4)  // 66.3 KB

__global__ void __launch_bounds__(128, 3) k_encoder(
    const float* __restrict__ x,
    const float* __restrict__ lW1, const float* __restrict__ lb1,
    const float* __restrict__ lW2, const float* __restrict__ lb2,
    const float* __restrict__ pW1, const float* __restrict__ pb1,
    const float* __restrict__ pW2, const float* __restrict__ pb2,
    float* __restrict__ hout)
{
    extern __shared__ float smem[];
    float* sWreg = smem;                 // 8192 floats (phase-dependent)
    float* sT    = smem + 8192;          // 128*65
    float* sB    = smem + 8192 + 128 * PADT;  // 256

    const int tid = threadIdx.x;
    const int n0 = blockIdx.x * 128;
    const int node = n0 + tid;
    const bool valid = node < NN;

    float* sWl1 = sWreg;            // 2624
    float* sWp1 = sWreg + 2624;
    for (int i = tid; i < 656; i += 128) {
        ((float4*)sWl1)[i] = __ldg(((const float4*)lW1) + i);
        ((float4*)sWp1)[i] = __ldg(((const float4*)pW1) + i);
    }
    if (tid < HH) {
        sB[tid] = __ldg(&lb1[tid]); sB[64 + tid] = __ldg(&pb1[tid]);
        sB[128 + tid] = __ldg(&lb2[tid]); sB[192 + tid] = __ldg(&pb2[tid]);
    }
    for (int c = tid; c < 128 * IN_CH; c += 128) {
        int n = c / IN_CH, k = c - n * IN_CH;
        sT[n * PADT + k] = (n0 + n < NN) ? __ldg(&x[(size_t)(n0 + n) * IN_CH + k]) : 0.f;
    }
    __syncthreads();

    float* trow = sT + tid * PADT;
    float s = 0.f;
#pragma unroll
    for (int k = ATOM; k < IN_CH; k++) s += fabsf(trow[k]);
    const bool prot = s > 1e-6f;
    const float* sW1 = prot ? sWp1 : sWl1;
    const float* b1 = prot ? (sB + 64) : sB;
    const float* b2 = prot ? (sB + 192) : (sB + 128);

    unsigned long long acc[32];
#pragma unroll
    for (int j = 0; j < 32; j++) acc[j] = pack2(b1[2 * j], b1[2 * j + 1]);
    for (int k = 0; k < IN_CH; k++) {
        float zv = trow[k];
        kstep(sW1 + k * HH, pack2(zv, zv), acc);
    }
    float tv[HH];
#pragma unroll
    for (int j = 0; j < 32; j++) {
        float lo, hi; unpack2(acc[j], lo, hi);
        tv[2 * j] = fmaxf(lo, 0.f);
        tv[2 * j + 1] = fmaxf(hi, 0.f);
    }
    __syncthreads();  // GEMM1 W reads done block-wide

    // phase 2: W2 into same region
    float* sWl2 = sWreg;
    float* sWp2 = sWreg + 4096;
    for (int i = tid; i < 1024; i += 128) {
        ((float4*)sWl2)[i] = __ldg(((const float4*)lW2) + i);
        ((float4*)sWp2)[i] = __ldg(((const float4*)pW2) + i);
    }
    // scalar stores: trow has odd stride (65), NOT 16B-aligned -> no vector STS
#pragma unroll
    for (int j = 0; j < HH; j++) trow[j] = tv[j];
    __syncthreads();

    const float* sW2 = prot ? sWp2 : sWl2;
#pragma unroll
    for (int j = 0; j < 32; j++) acc[j] = pack2(b2[2 * j], b2[2 * j + 1]);
    for (int k = 0; k < HH; k++) {
        float zv = trow[k];
        kstep(sW2 + k * HH, pack2(zv, zv), acc);
    }
    if (valid) {
        float4* op = (float4*)(hout + (size_t)node * HH);
#pragma unroll
        for (int q = 0; q < 16; q++) {
            float a0, a1, a2, a3;
            unpack2(acc[2 * q], a0, a1);
            unpack2(acc[2 * q + 1], a2, a3);
            op[q] = make_float4(fmaxf(a0, 0.f), fmaxf(a1, 0.f),
                                fmaxf(a2, 0.f), fmaxf(a3, 0.f));
        }
    }
}

// ================= edge kernel: W in registers, f32x2 FMAs ===================
__global__ void __launch_bounds__(256) k_edge(
    const float* __restrict__ h,
    const int* __restrict__ src, const int* __restrict__ dst,
    const float* __restrict__ ea,
    const float* __restrict__ We, const float* __restrict__ be,
    float* __restrict__ aggr)
{
    __shared__ __align__(16) float sW[ED * HH];
    __shared__ __align__(16) float sB[HH];
    for (int i = threadIdx.x; i < ED * HH; i += 256) sW[i] = We[i];
    if (threadIdx.x < HH) sB[threadIdx.x] = be[threadIdx.x];
    __syncthreads();

    const int le = threadIdx.x >> 4;
    const int lf = (threadIdx.x & 15) * 4;

    // preload W slice (8 k x 4 outs) into 16 packed regs
    unsigned long long wreg[16];
#pragma unroll
    for (int k = 0; k < 8; k++)
        lds_2u64(wreg[2 * k], wreg[2 * k + 1], &sW[k * HH + lf]);
    const unsigned long long bias0 = pack2(sB[lf], sB[lf + 1]);
    const unsigned long long bias1 = pack2(sB[lf + 2], sB[lf + 3]);

    const int stride = gridDim.x * 16;
    for (int e = blockIdx.x * 16 + le; e < EE; e += stride) {
        int s = __ldg(&src[e]);
        int d = __ldg(&dst[e]);
        const float4* eap = reinterpret_cast<const float4*>(ea + (size_t)e * ED);
        float4 a0 = __ldg(&eap[0]);
        float4 a1 = __ldg(&eap[1]);
        float4 hv = __ldg(reinterpret_cast<const float4*>(h + (size_t)s * HH + lf));
        unsigned long long acc0 = bias0, acc1 = bias1;
#pragma unroll
        for (int k = 0; k < 4; k++) {
            unsigned long long aa = pack2((&a0.x)[k], (&a0.x)[k]);
            ffma2(acc0, aa, wreg[2 * k]);
            ffma2(acc1, aa, wreg[2 * k + 1]);
        }
#pragma unroll
        for (int k = 0; k < 4; k++) {
            unsigned long long aa = pack2((&a1.x)[k], (&a1.x)[k]);
            ffma2(acc0, aa, wreg[8 + 2 * k]);
            ffma2(acc1, aa, wreg[8 + 2 * k + 1]);
        }
        float c0, c1v, c2, c3;
        unpack2(acc0, c0, c1v);
        unpack2(acc1, c2, c3);
        float m0 = fmaxf(hv.x + c0, 0.f);
        float m1 = fmaxf(hv.y + c1v, 0.f);
        float m2 = fmaxf(hv.z + c2, 0.f);
        float m3 = fmaxf(hv.w + c3, 0.f);
        float* p = aggr + (size_t)d * HH + lf;
        asm volatile("red.global.add.v4.f32 [%0], {%1,%2,%3,%4};"
                     :: "l"(p), "f"(m0), "f"(m1), "f"(m2), "f"(m3) : "memory");
    }
}

// ================= GraphNorm: chunked stats -> S,Q ==========================
__global__ void __launch_bounds__(256) k_stats(
    const float* __restrict__ h2, const int* __restrict__ batch,
    float* __restrict__ SQ)
{
    const int c0 = blockIdx.x * 256;
    const int cend = (c0 + 256 < NN) ? c0 + 256 : NN;
    const int tid = threadIdx.x;
    const int f = tid & 63;
    const int slot = tid >> 6;

    const int g0 = __ldg(&batch[c0]);
    const int g1 = __ldg(&batch[cend - 1]);
    const int span = g1 - g0 + 1;

    __shared__ float sS[8 * 64], sQ[8 * 64];
    if (span <= 8) {
        for (int i = tid; i < 512; i += 256) { sS[i] = 0.f; sQ[i] = 0.f; }
        __syncthreads();
        for (int i = c0 + slot; i < cend; i += 4) {
            float v = __ldg(&h2[(size_t)i * HH + f]);
            int gi = __ldg(&batch[i]) - g0;
            atomicAdd(&sS[gi * 64 + f], v);
            atomicAdd(&sQ[gi * 64 + f], v * v);
        }
        __syncthreads();
        for (int i2 = tid; i2 < span * 64; i2 += 256) {
            int gg = g0 + (i2 >> 6);
            atomicAdd(&SQ[gg * 64 + (i2 & 63)], sS[i2]);
            atomicAdd(&SQ[GG * HH + gg * 64 + (i2 & 63)], sQ[i2]);
        }
    } else {
        for (int i = c0 + slot; i < cend; i += 4) {
            float v = __ldg(&h2[(size_t)i * HH + f]);
            int gg = __ldg(&batch[i]);
            atomicAdd(&SQ[gg * 64 + f], v);
            atomicAdd(&SQ[GG * HH + gg * 64 + f], v * v);
        }
    }
}

__global__ void k_counts(const int* __restrict__ batch, float* __restrict__ cnt)
{
    int g = blockIdx.x * blockDim.x + threadIdx.x;
    if (g >= GG) return;
    int a = lower_bound_dev(batch, NN, g);
    int b = lower_bound_dev(batch, NN, g + 1);
    int c = b - a;
    cnt[g] = (float)(c > 0 ? c : 1);
}

__global__ void __launch_bounds__(256) k_coef(
    const float* __restrict__ SQ, const float* __restrict__ cnt,
    const float* __restrict__ w, const float* __restrict__ b,
    const float* __restrict__ alpha, float* __restrict__ coef)
{
    int idx = blockIdx.x * 256 + threadIdx.x;
    int g = idx >> 6, f = idx & 63;
    float c = __ldg(&cnt[g]);
    float S = __ldg(&SQ[idx]);
    float Q = __ldg(&SQ[GG * HH + idx]);
    float m = S / c;
    float m2 = Q / c;
    float a = __ldg(&alpha[f]);
    float var = m2 - m * m * a * (2.0f - a);
    float rstd = rsqrtf(var + EPSN);
    float wf = __ldg(&w[f]);
    coef[idx] = wf * rstd;
    coef[GG * HH + idx] = __ldg(&b[f]) - wf * rstd * a * m;
}

__global__ void __launch_bounds__(256) k_apply(
    const float* __restrict__ h2, const int* __restrict__ batch,
    const float* __restrict__ coef, float* __restrict__ hout)
{
    int idx = blockIdx.x * 256 + threadIdx.x;
    if (idx >= NN * 16) return;
    int node = idx >> 4, q = idx & 15;
    int g = __ldg(&batch[node]);
    float4 v = __ldg(((const float4*)h2) + idx);
    float4 c1 = __ldg(((const float4*)coef) + g * 16 + q);
    float4 c2 = __ldg(((const float4*)(coef + GG * HH)) + g * 16 + q);
    float4 o;
    o.x = fmaxf(fmaf(c1.x, v.x, c2.x), 0.f);
    o.y = fmaxf(fmaf(c1.y, v.y, c2.y), 0.f);
    o.z = fmaxf(fmaf(c1.z, v.z, c2.z), 0.f);
    o.w = fmaxf(fmaf(c1.w, v.w, c2.w), 0.f);
    ((float4*)hout)[idx] = o;
}

__global__ void __launch_bounds__(128) k_readout(
    const float* __restrict__ h, const int* __restrict__ batch,
    const float* __restrict__ W1, const float* __restrict__ b1,
    const float* __restrict__ W2, const float* __restrict__ b2,
    float* __restrict__ out)
{
    const int g = blockIdx.x;
    const int tid = threadIdx.x;
    __shared__ int sRange[2];
    if (tid < 2) sRange[tid] = lower_bound_dev(batch, NN, g + tid);
    __syncthreads();
    const int start = sRange[0], end = sRange[1];

    const int f = tid & 63;
    const int slot = tid >> 6;
    float s = 0.f;
    for (int i = start + slot; i < end; i += 2)
        s += __ldg(&h[(size_t)i * HH + f]);

    __shared__ float sp[128];
    __shared__ float pool[HH];
    __shared__ float tvs[HH];
    sp[tid] = s;
    __syncthreads();
    if (tid < HH) pool[tid] = sp[tid] + sp[tid + 64];
    __syncthreads();
    if (tid < HH) {
        float acc = __ldg(&b1[tid]);
#pragma unroll
        for (int k = 0; k < HH; k++)
            acc = fmaf(pool[k], __ldg(&W1[k * HH + tid]), acc);
        tvs[tid] = fmaxf(acc, 0.f) * __ldg(&W2[tid]);
    }
    __syncthreads();
    if (tid == 0) {
        float r = __ldg(b2);
#pragma unroll
        for (int k = 0; k < HH; k++) r += tvs[k];
        out[g] = r;
    }
}

// ================= launch ====================================================
extern "C" void kernel_launch(void* const* d_in, const int* in_sizes, int n_in,
                              void* d_out, int out_size)
{
    const float* x       = (const float*)d_in[0];
    const int*   ei      = (const int*)d_in[1];
    const float* ea      = (const float*)d_in[2];
    const int*   batch   = (const int*)d_in[3];
    const float* lig_W1  = (const float*)d_in[4];
    const float* lig_b1  = (const float*)d_in[5];
    const float* lig_W2  = (const float*)d_in[6];
    const float* lig_b2  = (const float*)d_in[7];
    const float* prot_W1 = (const float*)d_in[8];
    const float* prot_b1 = (const float*)d_in[9];
    const float* prot_W2 = (const float*)d_in[10];
    const float* prot_b2 = (const float*)d_in[11];
    const float* conv_We = (const float*)d_in[12];
    const float* conv_be = (const float*)d_in[13];
    const float* conv_W1 = (const float*)d_in[14];
    const float* conv_b1 = (const float*)d_in[15];
    const float* conv_W2 = (const float*)d_in[16];
    const float* conv_b2 = (const float*)d_in[17];
    const float* norm_w  = (const float*)d_in[18];
    const float* norm_b  = (const float*)d_in[19];
    const float* norm_a  = (const float*)d_in[20];
    const float* out_W1  = (const float*)d_in[21];
    const float* out_b1  = (const float*)d_in[22];
    const float* out_W2  = (const float*)d_in[23];
    const float* out_b2  = (const float*)d_in[24];
    float* out = (float*)d_out;

    const int* src = ei;
    const int* dst = ei + EE;

    void *ph, *ph2, *pag, *psq, *pcoef, *pcnt;
    cudaGetSymbolAddress(&ph,   g_hbuf);
    cudaGetSymbolAddress(&ph2,  g_h2buf);
    cudaGetSymbolAddress(&pag,  g_aggrbuf);
    cudaGetSymbolAddress(&psq,  g_SQ);
    cudaGetSymbolAddress(&pcoef, g_coef);
    cudaGetSymbolAddress(&pcnt, g_cnt);
    float* h    = (float*)ph;
    float* h2   = (float*)ph2;
    float* aggr = (float*)pag;
    float* SQ   = (float*)psq;
    float* coef = (float*)pcoef;
    float* cnt  = (float*)pcnt;

    static bool attr_done = false;
    if (!attr_done) {
        cudaFuncSetAttribute(k_mlp, cudaFuncAttributeMaxDynamicSharedMemorySize, MLP_SMEM);
        cudaFuncSetAttribute(k_encoder, cudaFuncAttributeMaxDynamicSharedMemorySize, ENC_SMEM);
        attr_done = true;
    }

    const int nodeBlocks = (NN + 127) / 128;   // 782
    const int edgeBlocks = 148 * 8;
    const int applyBlocks = (NN * 16 + 255) / 256;

    k_counts<<<1, 256>>>(batch, cnt);
    k_encoder<<<nodeBlocks, 128, ENC_SMEM>>>(x, lig_W1, lig_b1, lig_W2, lig_b2,
                                             prot_W1, prot_b1, prot_W2, prot_b2, h);

    for (int l = 0; l < LL; l++) {
        cudaMemsetAsync(aggr, 0, (size_t)NN * HH * sizeof(float));
        k_edge<<<edgeBlocks, 256>>>(h, src, dst, ea,
                                    conv_We + l * ED * HH, conv_be + l * HH, aggr);
        k_mlp<<<nodeBlocks, 128, MLP_SMEM>>>(h, aggr, conv_W1 + l * HH * HH,
                                             conv_b1 + l * HH,
                                             conv_W2 + l * HH * HH,
                                             conv_b2 + l * HH, h2);
        cudaMemsetAsync(SQ, 0, 2 * GG * HH * sizeof(float));
        k_stats<<<(NN + 255) / 256, 256>>>(h2, batch, SQ);
        k_coef<<<GG * HH / 256, 256>>>(SQ, cnt, norm_w + l * HH, norm_b + l * HH,
                                       norm_a + l * HH, coef);
        k_apply<<<applyBlocks, 256>>>(h2, batch, coef, h);
    }

    k_readout<<<GG, 128>>>(h, batch, out_W1, out_b1, out_W2, out_b2, out);
}